// round 3
// baseline (speedup 1.0000x reference)
#include <cuda_runtime.h>

// Problem constants (match reference)
#define NUM_CH   5
#define CROP_LO  70      // D//2 - 16, D = 173
#define CROP_HI  101     // CROP_LO + 32 - 1
#define CROP_N   32
#define CUBES    5
#define LATO     11      // 2*CUBES+1
#define RES2     0.0625f // RES*RES

#define SLABS    4
#define SLAB_X   8                          // CROP_N / SLABS
#define TILE_W   (SLAB_X * CROP_N * CROP_N) // 8192 floats = 32KB

// Single fused kernel: each block owns one (batch, channel, x-slab) tile of the
// output. Zero tile in smem -> splat atoms via smem atomics -> coalesced STG.
// No global memset, no global atomics, one graph node.
__global__ void __launch_bounds__(256) fused_voxelize_kernel(
    const float* __restrict__ coords,        // [B, N, 3]
    const int*   __restrict__ atoms_channel, // [B, N]
    const float* __restrict__ radius,        // [B, N]
    float* __restrict__ out,                 // [B, NUM_CH, 32, 32, 32]
    int n_per_batch)
{
    __shared__ float sm[TILE_W];

    const int tid  = threadIdx.x;
    const int slab = blockIdx.x & (SLABS - 1);
    const int bc   = blockIdx.x >> 2;            // b * NUM_CH + ch
    const int b    = bc / NUM_CH;
    const int ch   = bc - b * NUM_CH;

    // --- zero the tile ---
    float4* sm4 = (float4*)sm;
    #pragma unroll
    for (int i = tid; i < TILE_W / 4; i += 256)
        sm4[i] = make_float4(0.f, 0.f, 0.f, 0.f);
    __syncthreads();

    const int sx_lo = CROP_LO + slab * SLAB_X;   // slab x-range in grid cells
    const int sx_hi = sx_lo + SLAB_X - 1;

    const int warp = tid >> 5;
    const int lane = tid & 31;

    // --- splat: warp-per-atom round robin over this batch's atoms ---
    for (int a = warp; a < n_per_batch; a += 8) {
        const int atom = b * n_per_batch + a;
        if (atoms_channel[atom] != ch) continue;

        const float cx = coords[3 * atom + 0];
        const float cy = coords[3 * atom + 1];
        const float cz = coords[3 * atom + 2];

        // scaled = (c + BOX)/RES + (CUBES+1); /0.25 == *4 exactly
        const float sx = (cx + 20.0f) * 4.0f + 6.0f;
        const float sy = (cy + 20.0f) * 4.0f + 6.0f;
        const float sz = (cz + 20.0f) * 4.0f + 6.0f;
        const int bx = (int)floorf(sx) - CUBES;
        const int by = (int)floorf(sy) - CUBES;
        const int bz = (int)floorf(sz) - CUBES;

        // Clip splat box: x against this slab, y/z against crop window
        const int x0 = max(0, sx_lo  - bx), x1 = min(LATO - 1, sx_hi  - bx);
        const int y0 = max(0, CROP_LO - by), y1 = min(LATO - 1, CROP_HI - by);
        const int z0 = max(0, CROP_LO - bz), z1 = min(LATO - 1, CROP_HI - bz);
        const int nx = x1 - x0 + 1, ny = y1 - y0 + 1, nz = z1 - z0 + 1;
        if (nx <= 0 || ny <= 0 || nz <= 0) continue;

        const float r    = radius[atom];
        const float coef = 0.5f * RES2 / (r * r);
        // fractional offset of atom vs cell (b?+o?) center: f? - o?
        const float fx = sx - (float)(bx + x0) - 0.5f;
        const float fy = sy - (float)(by + y0) - 0.5f;
        const float fz = sz - (float)(bz + z0) - 0.5f;

        const int nyz  = ny * nz;
        const int ntot = nx * nyz;
        const float rnyz = 1.0f / (float)nyz;
        const float rnz  = 1.0f / (float)nz;

        // smem base at the clipped-box origin
        float* smp = sm + (((bx + x0 - sx_lo) * CROP_N + (by + y0 - CROP_LO)) * CROP_N
                           + (bz + z0 - CROP_LO));

        for (int k = lane; k < ntot; k += 32) {
            // exact small-int division via fp32 (k < 968, divisors <= 121)
            int ox  = (int)(((float)k + 0.5f) * rnyz);
            int rem = k - ox * nyz;
            int oy  = (int)(((float)rem + 0.5f) * rnz);
            int oz  = rem - oy * nz;
            float dx = fx - (float)ox;
            float dy = fy - (float)oy;
            float dz = fz - (float)oz;
            float d2 = fmaf(dx, dx, fmaf(dy, dy, dz * dz));
            float v  = __expf(-coef * d2);
            atomicAdd(&smp[(ox * CROP_N + oy) * CROP_N + oz], v);
        }
    }
    __syncthreads();

    // --- coalesced writeback: slab is contiguous in the output ---
    float4* dst = (float4*)(out + (size_t)bc * (CROP_N * CROP_N * CROP_N)
                                + (size_t)slab * TILE_W);
    #pragma unroll
    for (int i = tid; i < TILE_W / 4; i += 256)
        dst[i] = sm4[i];
}

extern "C" void kernel_launch(void* const* d_in, const int* in_sizes, int n_in,
                              void* d_out, int out_size) {
    const float* coords        = (const float*)d_in[0]; // [B,N,3]
    const int*   atoms_channel = (const int*)d_in[1];   // [B,N]
    const float* radius        = (const float*)d_in[2]; // [B,N]
    float* out = (float*)d_out;

    int n_atoms = in_sizes[1];                               // B*N
    int B = out_size / (NUM_CH * CROP_N * CROP_N * CROP_N);  // 8
    int n_per_batch = n_atoms / B;                           // 64

    int blocks = B * NUM_CH * SLABS;                         // 160
    fused_voxelize_kernel<<<blocks, 256>>>(coords, atoms_channel, radius, out,
                                           n_per_batch);
}